// round 5
// baseline (speedup 1.0000x reference)
#include <cuda_runtime.h>
#include <stdint.h>
#include <math.h>

#define NSTEP 16384
#define S     512
#define S2    256            // S/2 (float2 columns per thread)
#define LCH   32             // chunk length (timesteps stored per chain)
#define WARM  32             // warm-up steps (contraction ~0.05/step)
#define BCH   8              // chains batched per CTA (share A reads)
#define CPD   (NSTEP / LCH)  // 512 chunks per direction
#define CTAD  (CPD / BCH)    // 64 CTAs per direction
#define THREADS 256
#define NWARP  (THREADS / 32)

// Scratch (static device arrays; referenced ONLY from device code — the
// host-side use of these symbols was the bug in rounds 1-4)
__device__ float g_alphas[NSTEP * S];   // 32 MB
__device__ float g_AT[S * S];           // 1 MB transposed A

__device__ __forceinline__ float safe_inv(float s) {
    return (isfinite(s) && s > 0.f) ? __fdividef(1.0f, s) : 1.0f;
}

// ---------------- naive A transpose ----------------
__global__ void transpose_k(const float* __restrict__ A) {
    const int idx = blockIdx.x * blockDim.x + threadIdx.x;
    if (idx < S * S) {
        const int i = idx / S, j = idx % S;
        g_AT[j * S + i] = A[idx];
    }
}

// ---------------- chunked forward/backward scan (plain scalar fp32) ----------
// blockIdx.x in [0, CTAD)      : forward, chunks [qb, qb+BCH)
// blockIdx.x in [CTAD, 2*CTAD) : backward, chunks [qb, qb+BCH)
__global__ void __launch_bounds__(THREADS, 1) hmm_scan(
    const float* __restrict__ obs,
    const float* __restrict__ A,
    const float* __restrict__ pi0,
    float* __restrict__ betas_out)
{
    __shared__ __align__(16) float vsh[BCH][S];   // state vectors (16 KB)
    __shared__ float wred[BCH][NWARP];            // per-warp partial sums
    __shared__ float sinv[BCH];                   // per-chain 1/sum

    const int  tid  = threadIdx.x;
    const int  lane = tid & 31;
    const int  wrp  = tid >> 5;
    const bool bwd  = (blockIdx.x >= CTAD);
    const int  qb   = (bwd ? (int)blockIdx.x - CTAD : (int)blockIdx.x) * BCH;

    const float* __restrict__ M = bwd ? (const float*)g_AT : A;
    const float2* __restrict__ obs2  = (const float2*)obs;
    float2* __restrict__       alph2 = (float2*)g_alphas;
    float2* __restrict__       beta2 = (float2*)betas_out;

    // ---- init per-chain state ----
    #pragma unroll
    for (int c = 0; c < BCH; ++c) {
        if (!bwd) {
            vsh[c][2 * tid]     = 1.0f;   // uniform warm-up start
            vsh[c][2 * tid + 1] = 1.0f;
        } else {
            const int q    = qb + c;
            const int hi   = q * LCH + LCH - 1;
            const int ttop = min(NSTEP - 1, hi + WARM);
            const float2 o = obs2[ttop * S2 + tid];   // v = ones * obs[ttop]
            vsh[c][2 * tid]     = o.x;
            vsh[c][2 * tid + 1] = o.y;
            if (ttop == hi)                            // terminal chunk exact
                beta2[ttop * S2 + tid] = make_float2(1.f / S, 1.f / S);
        }
    }
    __syncthreads();

    const int kstart = bwd ? 1 : 0;
    for (int k = kstart; k < WARM + LCH; ++k) {
        // ===== phase 1: batched vecmat + emission + warp partials =====
        float acc0[BCH], acc1[BCH];
        #pragma unroll
        for (int c = 0; c < BCH; ++c) { acc0[c] = 0.f; acc1[c] = 0.f; }

        const float2* Ap = ((const float2*)M) + tid;   // column pair (2tid, 2tid+1)
        #pragma unroll 4
        for (int i = 0; i < S; i += 2) {
            const float2 m0 = Ap[i * S2];
            const float2 m1 = Ap[(i + 1) * S2];
            #pragma unroll
            for (int c = 0; c < BCH; ++c) {
                const float2 w = *(const float2*)&vsh[c][i];
                acc0[c] = fmaf(w.x, m0.x, acc0[c]);
                acc1[c] = fmaf(w.x, m0.y, acc1[c]);
                acc0[c] = fmaf(w.y, m1.x, acc0[c]);
                acc1[c] = fmaf(w.y, m1.y, acc1[c]);
            }
        }

        float2 r[BCH];
        bool   act[BCH];
        #pragma unroll
        for (int c = 0; c < BCH; ++c) {
            const int q = qb + c;
            act[c] = false;
            if (!bwd) {
                const int t = q * LCH + k - WARM;
                if (t < 0) continue;
                act[c] = true;
                if (t == 0) {                       // exact start of sequence
                    const float2 o  = obs2[tid];
                    const float2 pz = ((const float2*)pi0)[tid];
                    r[c] = make_float2(o.x * pz.x, o.y * pz.y);
                } else {
                    const float2 o = obs2[t * S2 + tid];
                    r[c] = make_float2(acc0[c] * o.x, acc1[c] * o.y);
                }
            } else {
                const int ttop = min(NSTEP - 1, q * LCH + LCH - 1 + WARM);
                const int t    = ttop - k;
                if (t < q * LCH) continue;
                act[c] = true;
                r[c] = make_float2(acc0[c], acc1[c]);
            }
            float sl = r[c].x + r[c].y;
            #pragma unroll
            for (int o = 16; o > 0; o >>= 1)
                sl += __shfl_xor_sync(0xffffffffu, sl, o);
            if (lane == 0) wred[c][wrp] = sl;
        }
        __syncthreads();

        // ===== phase 2: combine warp partials (threads 0..BCH-1) =====
        if (tid < BCH) {
            float s = 0.f;
            #pragma unroll
            for (int w = 0; w < NWARP; ++w) s += wred[tid][w];
            sinv[tid] = safe_inv(s);
        }
        __syncthreads();

        // ===== phase 3: normalize, update state, store =====
        #pragma unroll
        for (int c = 0; c < BCH; ++c) {
            if (!act[c]) continue;
            const int q = qb + c;
            const float inv = sinv[c];
            if (!bwd) {
                const int t = q * LCH + k - WARM;
                const float2 a = make_float2(r[c].x * inv, r[c].y * inv);
                vsh[c][2 * tid]     = a.x;
                vsh[c][2 * tid + 1] = a.y;
                if (k >= WARM) alph2[t * S2 + tid] = a;
            } else {
                const int ttop = min(NSTEP - 1, q * LCH + LCH - 1 + WARM);
                const int t    = ttop - k;
                const float2 b = make_float2(r[c].x * inv, r[c].y * inv);
                if (t <= q * LCH + LCH - 1) beta2[t * S2 + tid] = b;
                const float2 o = obs2[t * S2 + tid];   // fold obs[t] for next step
                vsh[c][2 * tid]     = b.x * o.x;
                vsh[c][2 * tid + 1] = b.y * o.y;
            }
        }
        __syncthreads();   // vsh writes & wred reuse vs next iteration
    }
}

// ---------------- gamma = normalize(alpha ⊙ beta) per row ----------------
// NOTE: g_alphas referenced directly from device code (NOT passed from host —
// a __device__ symbol used as a host-side kernel argument is the host shadow
// address, which ATS on GB300 happily reads as zeros).
__global__ void __launch_bounds__(256) gamma_kernel(float* __restrict__ io)
{
    __shared__ float wsum[8];
    const int t = blockIdx.x, tid = threadIdx.x;
    const int lane = tid & 31, w = tid >> 5;
    const float2* a2 = (const float2*)g_alphas;
    float2*       o2 = (float2*)io;

    const float2 a = a2[t * S2 + tid];
    const float2 b = o2[t * S2 + tid];
    const float2 pdt = make_float2(a.x * b.x, a.y * b.y);

    float s = pdt.x + pdt.y;
    #pragma unroll
    for (int o = 16; o > 0; o >>= 1) s += __shfl_xor_sync(0xffffffffu, s, o);
    if (lane == 0) wsum[w] = s;
    __syncthreads();
    if (w == 0) {
        float v = wsum[lane & 7];
        #pragma unroll
        for (int o = 4; o > 0; o >>= 1) v += __shfl_xor_sync(0xffffffffu, v, o);
        if (lane == 0) wsum[0] = v;
    }
    __syncthreads();
    const float inv = safe_inv(wsum[0]);
    o2[t * S2 + tid] = make_float2(pdt.x * inv, pdt.y * inv);
}

// ---------------- launch ----------------
extern "C" void kernel_launch(void* const* d_in, const int* in_sizes, int n_in,
                              void* d_out, int out_size)
{
    // Input resolution: match by element count (fall back to positional).
    const float* obs = nullptr; const float* A = nullptr; const float* pi0 = nullptr;
    for (int i = 0; i < n_in; ++i) {
        const long long sz = in_sizes[i];
        if      (sz == (long long)NSTEP * S) obs = (const float*)d_in[i];
        else if (sz == (long long)S * S)     A   = (const float*)d_in[i];
        else if (sz == (long long)S)         pi0 = (const float*)d_in[i];
    }
    if (!obs || !A || !pi0) {   // positional fallback: setup_inputs dict order
        obs = (const float*)d_in[0];
        A   = (const float*)d_in[1];
        pi0 = (const float*)d_in[2];
    }
    float* out = (float*)d_out;   // [16384, 512] f32 gammas

    transpose_k<<<(S * S + 255) / 256, 256>>>(A);
    hmm_scan<<<2 * CTAD, THREADS>>>(obs, A, pi0, out);   // betas land in d_out
    gamma_kernel<<<NSTEP, 256>>>(out);                   // in-place -> gammas
}

// round 6
// speedup vs baseline: 1.5428x; 1.5428x over previous
#include <cuda_runtime.h>
#include <stdint.h>
#include <math.h>

#define NSTEP 16384
#define S     512
#define S2    256            // S/2 (float2 columns per thread)
#define LCH   32             // chunk length (timesteps stored per chain)
#define WARM  12             // warm-up steps (contraction ~0.03-0.33/step -> <=2e-6)
#define BCH   8              // chains batched per CTA (share A reads)
#define CPD   (NSTEP / LCH)  // 512 chunks per direction
#define CTAD  (CPD / BCH)    // 64 CTAs per direction
#define THREADS 256

// Scratch (static device arrays; referenced ONLY from device code —
// host-side use of a __device__ symbol reads the host shadow via ATS)
__device__ float g_alphas[NSTEP * S];   // 32 MB
__device__ float g_AT[S * S];           // 1 MB transposed A

__device__ __forceinline__ float safe_inv(float s) {
    return (isfinite(s) && s > 0.f) ? __fdividef(1.0f, s) : 1.0f;
}

// ---------------- packed f32x2 helpers ----------------
__device__ __forceinline__ void fma2(unsigned long long &d,
                                     unsigned long long a,
                                     unsigned long long b) {
    asm("fma.rn.f32x2 %0, %1, %2, %0;" : "+l"(d) : "l"(a), "l"(b));
}
__device__ __forceinline__ unsigned long long bcast2(float x) {
    unsigned int u = __float_as_uint(x);
    return ((unsigned long long)u << 32) | (unsigned long long)u;
}
__device__ __forceinline__ float2 unpack2(unsigned long long v) {
    float2 r;
    r.x = __uint_as_float((unsigned int)v);
    r.y = __uint_as_float((unsigned int)(v >> 32));
    return r;
}

// ---------------- naive A transpose ----------------
__global__ void transpose_k(const float* __restrict__ A) {
    const int idx = blockIdx.x * blockDim.x + threadIdx.x;
    if (idx < S * S) {
        const int i = idx / S, j = idx % S;
        g_AT[j * S + i] = A[idx];
    }
}

// ---------------- chunked forward/backward scan, packed f32x2, no per-step norm ----
// blockIdx.x in [0, CTAD)      : forward, chunks [qb, qb+BCH)
// blockIdx.x in [CTAD, 2*CTAD) : backward, chunks [qb, qb+BCH)
// Normalization is dropped: gammas are invariant to per-row scaling of alpha/beta.
// A fixed x2 per-step rescale (folded into the emission multiply) keeps magnitudes
// near-constant (per-step log-drift sigma ~0.026, self-averaging over 512 states).
__global__ void __launch_bounds__(THREADS, 1) hmm_scan(
    const float* __restrict__ obs,
    const float* __restrict__ A,
    const float* __restrict__ pi0,
    float* __restrict__ betas_out)
{
    __shared__ __align__(16) unsigned long long vsh[BCH][S];  // {x,x}-packed, 32 KB

    const int  tid = threadIdx.x;
    const bool bwd = (blockIdx.x >= CTAD);
    const int  qb  = (bwd ? (int)blockIdx.x - CTAD : (int)blockIdx.x) * BCH;

    const unsigned long long* __restrict__ Mu =
        (const unsigned long long*)(bwd ? (const float*)g_AT : A);
    const float2* __restrict__ obs2  = (const float2*)obs;
    float2* __restrict__       alph2 = (float2*)g_alphas;
    float2* __restrict__       beta2 = (float2*)betas_out;

    // ---- init per-chain state ----
    #pragma unroll
    for (int c = 0; c < BCH; ++c) {
        ulonglong2 wv;
        if (!bwd) {
            wv.x = bcast2(1.0f); wv.y = bcast2(1.0f);      // uniform warm-up start
        } else {
            const int q    = qb + c;
            const int hi   = q * LCH + LCH - 1;
            const int ttop = min(NSTEP - 1, hi + WARM);
            const float2 o = obs2[ttop * S2 + tid];        // v = ones .* obs[ttop]
            wv.x = bcast2(o.x); wv.y = bcast2(o.y);
            if (ttop == hi)                                 // terminal chunk exact
                beta2[ttop * S2 + tid] = make_float2(1.f / S, 1.f / S);
        }
        *(ulonglong2*)&vsh[c][2 * tid] = wv;
    }
    __syncthreads();

    const int kstart = bwd ? 1 : 0;
    for (int k = kstart; k < WARM + LCH; ++k) {
        // ---- per-chain activity + obs prefetch (hides L2/DRAM under FMA loop) ----
        int    tt[BCH];
        bool   act[BCH];
        float2 o[BCH];
        #pragma unroll
        for (int c = 0; c < BCH; ++c) {
            const int q = qb + c;
            if (!bwd) {
                tt[c]  = q * LCH + k - WARM;
                act[c] = (tt[c] >= 0);
            } else {
                const int ttop = min(NSTEP - 1, q * LCH + LCH - 1 + WARM);
                tt[c]  = ttop - k;
                act[c] = (tt[c] >= q * LCH);
            }
            if (act[c]) o[c] = obs2[tt[c] * S2 + tid];
        }

        // ---- batched packed vecmat: acc[c] = sum_i vsh[c][i] * M[i][2tid..2tid+1] ----
        unsigned long long acc[BCH];
        #pragma unroll
        for (int c = 0; c < BCH; ++c) acc[c] = 0ull;

        const unsigned long long* Mp = Mu + tid;
        #pragma unroll 2
        for (int i0 = 0; i0 < S; i0 += 8) {
            unsigned long long m[8];
            #pragma unroll
            for (int u = 0; u < 8; ++u) m[u] = Mp[(i0 + u) * S2];
            #pragma unroll
            for (int c = 0; c < BCH; ++c) {
                const ulonglong2* wp = (const ulonglong2*)&vsh[c][i0];
                const ulonglong2 w0 = wp[0], w1 = wp[1], w2 = wp[2], w3 = wp[3];
                fma2(acc[c], w0.x, m[0]); fma2(acc[c], w0.y, m[1]);
                fma2(acc[c], w1.x, m[2]); fma2(acc[c], w1.y, m[3]);
                fma2(acc[c], w2.x, m[4]); fma2(acc[c], w2.y, m[5]);
                fma2(acc[c], w3.x, m[6]); fma2(acc[c], w3.y, m[7]);
            }
        }
        __syncthreads();   // all vsh reads complete before writes

        // ---- epilogue: emission multiply, store, state update (no reduction) ----
        #pragma unroll
        for (int c = 0; c < BCH; ++c) {
            if (!act[c]) continue;
            const float2 a = unpack2(acc[c]);
            ulonglong2 wv;
            if (!bwd) {
                float2 r;
                if (tt[c] == 0) {   // exact start of sequence: alpha0 = pi0 .* obs0
                    const float2 pz = ((const float2*)pi0)[tid];
                    r = make_float2(o[c].x * pz.x * 2.f, o[c].y * pz.y * 2.f);
                } else {            // alpha_t = (alpha_{t-1} @ A) .* obs_t, x2 rescale
                    r = make_float2(a.x * (o[c].x + o[c].x),
                                    a.y * (o[c].y + o[c].y));
                }
                if (k >= WARM) alph2[tt[c] * S2 + tid] = r;
                wv.x = bcast2(r.x); wv.y = bcast2(r.y);
            } else {
                // beta_t = A @ (beta_{t+1} .* obs_{t+1})  (obs folded below)
                if (tt[c] <= qb * LCH + c * LCH + LCH - 1)
                    beta2[tt[c] * S2 + tid] = a;
                wv.x = bcast2(a.x * (o[c].x + o[c].x));   // fold obs_t, x2 rescale
                wv.y = bcast2(a.y * (o[c].y + o[c].y));
            }
            *(ulonglong2*)&vsh[c][2 * tid] = wv;
        }
        __syncthreads();   // vsh writes complete before next step's reads
    }
}

// ---------------- gamma = normalize(alpha .* beta) per row ----------------
__global__ void __launch_bounds__(256) gamma_kernel(float* __restrict__ io)
{
    __shared__ float wsum[8];
    const int t = blockIdx.x, tid = threadIdx.x;
    const int lane = tid & 31, w = tid >> 5;
    const float2* a2 = (const float2*)g_alphas;   // device-symbol reference
    float2*       o2 = (float2*)io;

    const float2 a = a2[t * S2 + tid];
    const float2 b = o2[t * S2 + tid];
    const float2 pdt = make_float2(a.x * b.x, a.y * b.y);

    float s = pdt.x + pdt.y;
    #pragma unroll
    for (int o = 16; o > 0; o >>= 1) s += __shfl_xor_sync(0xffffffffu, s, o);
    if (lane == 0) wsum[w] = s;
    __syncthreads();
    if (w == 0) {
        float v = wsum[lane & 7];
        #pragma unroll
        for (int o = 4; o > 0; o >>= 1) v += __shfl_xor_sync(0xffffffffu, v, o);
        if (lane == 0) wsum[0] = v;
    }
    __syncthreads();
    const float inv = safe_inv(wsum[0]);
    o2[t * S2 + tid] = make_float2(pdt.x * inv, pdt.y * inv);
}

// ---------------- launch ----------------
extern "C" void kernel_launch(void* const* d_in, const int* in_sizes, int n_in,
                              void* d_out, int out_size)
{
    const float* obs = nullptr; const float* A = nullptr; const float* pi0 = nullptr;
    for (int i = 0; i < n_in; ++i) {
        const long long sz = in_sizes[i];
        if      (sz == (long long)NSTEP * S) obs = (const float*)d_in[i];
        else if (sz == (long long)S * S)     A   = (const float*)d_in[i];
        else if (sz == (long long)S)         pi0 = (const float*)d_in[i];
    }
    if (!obs || !A || !pi0) {
        obs = (const float*)d_in[0];
        A   = (const float*)d_in[1];
        pi0 = (const float*)d_in[2];
    }
    float* out = (float*)d_out;   // [16384, 512] f32 gammas

    transpose_k<<<(S * S + 255) / 256, 256>>>(A);
    hmm_scan<<<2 * CTAD, THREADS>>>(obs, A, pi0, out);   // betas land in d_out
    gamma_kernel<<<NSTEP, 256>>>(out);                   // in-place -> gammas
}